// round 1
// baseline (speedup 1.0000x reference)
#include <cuda_runtime.h>
#include <math_constants.h>

#define BB  16
#define SS  1024
#define DD  1024
#define HH  16
#define DKK 64

// Scratch (allocation-free rule: __device__ globals). 4 x 64MB.
__device__ float g_Q[BB*HH*SS*DKK];
__device__ float g_K[BB*HH*SS*DKK];
__device__ float g_V[BB*HH*SS*DKK];
__device__ float g_O[BB*SS*HH*DKK];

// ---------------------------------------------------------------------------
// SGEMM: C = A[MxK] * W[KxN], row-major. 128x128 block, 8x8 per thread, BK=8.
// PERMUTE=true: scatter output [B*S, H*DK] -> [B,H,S,DK] layout.
// ---------------------------------------------------------------------------
template<bool PERMUTE>
__global__ __launch_bounds__(256, 2)
void sgemm_kernel(const float* __restrict__ A, const float* __restrict__ W,
                  float* __restrict__ C, int M, int N, int K)
{
    constexpr int BM = 128, BN = 128, BK = 8, TM = 8, TN = 8;
    __shared__ float As[BK][BM];
    __shared__ float Bs[BK][BN];

    const int tid = threadIdx.x;
    const int bx = blockIdx.x, by = blockIdx.y;
    const int tx = tid & 15, ty = tid >> 4;

    float acc[TM][TN] = {};

    const int a_row = tid >> 1;          // 0..127
    const int a_col = (tid & 1) << 2;    // 0 or 4
    const int b_row = tid >> 5;          // 0..7
    const int b_col = (tid & 31) << 2;   // 0..124

    const float* Ap = A + (size_t)(by * BM + a_row) * K + a_col;
    const float* Wp = W + (size_t)b_row * N + bx * BN + b_col;

    for (int k0 = 0; k0 < K; k0 += BK) {
        float4 av = *(const float4*)(Ap + k0);
        float4 bv = *(const float4*)(Wp + (size_t)k0 * N);
        As[a_col + 0][a_row] = av.x;
        As[a_col + 1][a_row] = av.y;
        As[a_col + 2][a_row] = av.z;
        As[a_col + 3][a_row] = av.w;
        *(float4*)&Bs[b_row][b_col] = bv;
        __syncthreads();

        #pragma unroll
        for (int kk = 0; kk < BK; kk++) {
            float ra[TM], rb[TN];
            #pragma unroll
            for (int i = 0; i < TM; i++) ra[i] = As[kk][ty * TM + i];
            #pragma unroll
            for (int j = 0; j < TN; j++) rb[j] = Bs[kk][tx * TN + j];
            #pragma unroll
            for (int i = 0; i < TM; i++)
                #pragma unroll
                for (int j = 0; j < TN; j++)
                    acc[i][j] = fmaf(ra[i], rb[j], acc[i][j]);
        }
        __syncthreads();
    }

    const int n0 = bx * BN + tx * TN;    // 8 consecutive cols, never crossing a 64 boundary
    #pragma unroll
    for (int i = 0; i < TM; i++) {
        const int m = by * BM + ty * TM + i;
        float4 v0 = make_float4(acc[i][0], acc[i][1], acc[i][2], acc[i][3]);
        float4 v1 = make_float4(acc[i][4], acc[i][5], acc[i][6], acc[i][7]);
        if (!PERMUTE) {
            float* p = C + (size_t)m * N + n0;
            *(float4*)(p)     = v0;
            *(float4*)(p + 4) = v1;
        } else {
            const int b  = m >> 10;        // m / S
            const int s  = m & 1023;       // m % S
            const int h  = n0 >> 6;        // n / DK
            const int dk = n0 & 63;        // n % DK (8-aligned, stays within one h)
            float* p = C + ((size_t)(b * HH + h) * SS + s) * DKK + dk;
            *(float4*)(p)     = v0;
            *(float4*)(p + 4) = v1;
        }
    }
}

// ---------------------------------------------------------------------------
// Flash attention: block = (q-tile of 64 rows) x (head h) x (batch b).
// 64 threads, one q-row per thread; q and o accumulators in registers.
// Online softmax with one rescale per 64-key tile.
// smem = Ks(16K) + Vs(16K) + Sc(16K) = 48KB exactly.
// ---------------------------------------------------------------------------
__global__ __launch_bounds__(64)
void flash_kernel(const float* __restrict__ bias, const float* __restrict__ bt,
                  float* __restrict__ O)
{
    constexpr int BQ = 64, BKV = 64;
    __shared__ float Ks[BKV][DKK];
    __shared__ float Vs[BKV][DKK];
    __shared__ float Sc[BKV][BQ];   // transposed: Sc[j][t] -> conflict-free LDS/STS

    const int t  = threadIdx.x;
    const int qb = blockIdx.x * BQ;
    const int h  = blockIdx.y;
    const int b  = blockIdx.z;

    // Load this thread's q row into registers.
    const float* Qp = g_Q + ((size_t)(b * HH + h) * SS + qb + t) * DKK;
    float q[DKK];
    #pragma unroll
    for (int d = 0; d < DKK; d += 4) {
        float4 v = *(const float4*)(Qp + d);
        q[d] = v.x; q[d+1] = v.y; q[d+2] = v.z; q[d+3] = v.w;
    }

    const float  btv     = bt[h];
    const float* biasRow = bias + (size_t)(qb + t) * SS;

    float m = -CUDART_INF_F;
    float l = 0.f;
    float o[DKK] = {};

    const float* Kb = g_K + (size_t)(b * HH + h) * SS * DKK;
    const float* Vb = g_V + (size_t)(b * HH + h) * SS * DKK;

    for (int kb = 0; kb < SS; kb += BKV) {
        __syncthreads();  // previous tile fully consumed before overwrite
        // Cooperative load of K/V tiles: 1024 float4 each / 64 threads.
        #pragma unroll
        for (int u = 0; u < 16; u++) {
            const int idx = t + u * 64;          // 0..1023
            const int row = idx >> 4;            // /16
            const int c4  = (idx & 15) << 2;
            *(float4*)&Ks[row][c4] = *(const float4*)(Kb + (size_t)(kb + row) * DKK + c4);
            *(float4*)&Vs[row][c4] = *(const float4*)(Vb + (size_t)(kb + row) * DKK + c4);
        }
        __syncthreads();

        // Pass 1: scores for 64 keys; track tile max. Bias via LDG.128 (L2-resident).
        float tmax = m;
        #pragma unroll 1
        for (int j4 = 0; j4 < BKV; j4 += 4) {
            float4 bv = *(const float4*)(biasRow + kb + j4);
            float bb4[4] = {bv.x, bv.y, bv.z, bv.w};
            #pragma unroll
            for (int jj = 0; jj < 4; jj++) {
                const int j = j4 + jj;
                const float4* Kr = (const float4*)Ks[j];
                float s0 = 0.f, s1 = 0.f, s2 = 0.f, s3 = 0.f;
                #pragma unroll
                for (int d4 = 0; d4 < 16; d4++) {
                    float4 kv = Kr[d4];
                    s0 = fmaf(q[d4*4+0], kv.x, s0);
                    s1 = fmaf(q[d4*4+1], kv.y, s1);
                    s2 = fmaf(q[d4*4+2], kv.z, s2);
                    s3 = fmaf(q[d4*4+3], kv.w, s3);
                }
                float s = fmaf(btv, bb4[jj], ((s0 + s1) + (s2 + s3)) * 0.125f);
                Sc[j][t] = s;
                tmax = fmaxf(tmax, s);
            }
        }

        // Rescale running state once per tile.
        const float scale = __expf(m - tmax);   // first tile: exp(-inf)=0
        m = tmax;
        l *= scale;
        #pragma unroll
        for (int d = 0; d < DKK; d++) o[d] *= scale;

        // Pass 2: exp + accumulate P*V.
        #pragma unroll 1
        for (int j = 0; j < BKV; j++) {
            const float p = __expf(Sc[j][t] - m);
            l += p;
            const float4* Vr = (const float4*)Vs[j];
            #pragma unroll
            for (int d4 = 0; d4 < 16; d4++) {
                float4 vv = Vr[d4];
                o[d4*4+0] = fmaf(p, vv.x, o[d4*4+0]);
                o[d4*4+1] = fmaf(p, vv.y, o[d4*4+1]);
                o[d4*4+2] = fmaf(p, vv.z, o[d4*4+2]);
                o[d4*4+3] = fmaf(p, vv.w, o[d4*4+3]);
            }
        }
    }

    // Normalize and store in [B, S, H*DK] layout (ready for the output GEMM).
    const float inv = 1.f / l;
    float* Op = O + ((size_t)(b * SS) + qb + t) * (HH * DKK) + h * DKK;
    #pragma unroll
    for (int d = 0; d < DKK; d += 4) {
        float4 v = make_float4(o[d]*inv, o[d+1]*inv, o[d+2]*inv, o[d+3]*inv);
        *(float4*)(Op + d) = v;
    }
}

// ---------------------------------------------------------------------------
// Launch: X@Wq/Wk/Wv (permuted store) -> flash attention -> O@Wo -> d_out.
// Graph-capturable: kernel launches only.
// ---------------------------------------------------------------------------
extern "C" void kernel_launch(void* const* d_in, const int* in_sizes, int n_in,
                              void* d_out, int out_size)
{
    (void)in_sizes; (void)n_in; (void)out_size;
    const float* X    = (const float*)d_in[0];
    const float* bias = (const float*)d_in[1];
    const float* Wq   = (const float*)d_in[2];
    const float* Wk   = (const float*)d_in[3];
    const float* Wv   = (const float*)d_in[4];
    const float* Wo   = (const float*)d_in[5];
    const float* bt   = (const float*)d_in[6];
    float* out = (float*)d_out;

    float *Qp, *Kp, *Vp, *Op;
    cudaGetSymbolAddress((void**)&Qp, g_Q);
    cudaGetSymbolAddress((void**)&Kp, g_K);
    cudaGetSymbolAddress((void**)&Vp, g_V);
    cudaGetSymbolAddress((void**)&Op, g_O);

    dim3 ggrid(DD / 128, (BB * SS) / 128);   // (8, 128)
    sgemm_kernel<true><<<ggrid, 256>>>(X, Wq, Qp, BB * SS, DD, DD);
    sgemm_kernel<true><<<ggrid, 256>>>(X, Wk, Kp, BB * SS, DD, DD);
    sgemm_kernel<true><<<ggrid, 256>>>(X, Wv, Vp, BB * SS, DD, DD);

    flash_kernel<<<dim3(SS / 64, HH, BB), 64>>>(bias, bt, Op);

    sgemm_kernel<false><<<ggrid, 256>>>(Op, Wo, out, BB * SS, DD, DD);
}

// round 4
// speedup vs baseline: 1.4693x; 1.4693x over previous
#include <cuda_runtime.h>
#include <cuda_bf16.h>
#include <math_constants.h>
#include <cstdint>

#define BB  16
#define SS  1024
#define DD  1024
#define HH  16
#define DKK 64
#define MM  (BB*SS)          // 16384

// ---------------- scratch (__device__ globals; no runtime allocs) ----------
__device__ float g_Q[BB*HH*SS*DKK];
__device__ float g_K[BB*HH*SS*DKK];
__device__ float g_V[BB*HH*SS*DKK];
__device__ float g_O[MM*DD];
__device__ __nv_bfloat16 g_Ah[MM*DD];     // hi of X, later hi of O
__device__ __nv_bfloat16 g_Al[MM*DD];     // lo of X, later lo of O
__device__ __nv_bfloat16 g_Wh[4][DD*DD];  // transposed weights, hi
__device__ __nv_bfloat16 g_Wl[4][DD*DD];  // transposed weights, lo

// ---------------- PTX helpers (sm_80-era only: valid in base sm_103 PTX) ---
__device__ __forceinline__ uint32_t cvta_s(const void* p) {
    return (uint32_t)__cvta_generic_to_shared(p);
}
#define CP_ASYNC16(saddr, gptr) \
    asm volatile("cp.async.cg.shared.global [%0], [%1], 16;" \
                 :: "r"((uint32_t)(saddr)), "l"(gptr))
#define CP_ASYNC_COMMIT() asm volatile("cp.async.commit_group;" ::: "memory")
#define CP_ASYNC_WAIT(n)  asm volatile("cp.async.wait_group %0;" :: "n"(n) : "memory")

#define LDMATRIX_X4(r0, r1, r2, r3, addr) \
    asm volatile("ldmatrix.sync.aligned.m8n8.x4.shared.b16 {%0,%1,%2,%3}, [%4];" \
                 : "=r"(r0), "=r"(r1), "=r"(r2), "=r"(r3) : "r"(addr))
#define LDMATRIX_X2(r0, r1, addr) \
    asm volatile("ldmatrix.sync.aligned.m8n8.x2.shared.b16 {%0,%1}, [%2];" \
                 : "=r"(r0), "=r"(r1) : "r"(addr))

#define MMA_BF16(d, a, b) \
    asm volatile("mma.sync.aligned.m16n8k16.row.col.f32.bf16.bf16.f32 " \
        "{%0,%1,%2,%3}, {%4,%5,%6,%7}, {%8,%9}, {%0,%1,%2,%3};" \
        : "+f"((d)[0]), "+f"((d)[1]), "+f"((d)[2]), "+f"((d)[3]) \
        : "r"((a)[0]), "r"((a)[1]), "r"((a)[2]), "r"((a)[3]), \
          "r"((b)[0]), "r"((b)[1]))

// ---------------- fp32 -> bf16 hi/lo split ---------------------------------
__global__ __launch_bounds__(256)
void convert_hl_kernel(const float* __restrict__ X,
                       __nv_bfloat16* __restrict__ H, __nv_bfloat16* __restrict__ L)
{
    const size_t i = ((size_t)blockIdx.x * 256 + threadIdx.x) * 4;
    float4 v = *(const float4*)(X + i);
    float f[4] = {v.x, v.y, v.z, v.w};
    ushort4 hv, lv;
    unsigned short* hp = &hv.x; unsigned short* lp = &lv.x;
    #pragma unroll
    for (int j = 0; j < 4; j++) {
        __nv_bfloat16 h = __float2bfloat16(f[j]);
        float r = f[j] - __bfloat162float(h);
        hp[j] = __bfloat16_as_ushort(h);
        lp[j] = __bfloat16_as_ushort(__float2bfloat16(r));
    }
    *(ushort4*)(H + i) = hv;
    *(ushort4*)(L + i) = lv;
}

// ---------------- W [K,N] -> W^T [N,K], split hi/lo ------------------------
__global__ __launch_bounds__(256)
void convert_wt_kernel(const float* __restrict__ W,
                       __nv_bfloat16* __restrict__ Th, __nv_bfloat16* __restrict__ Tl)
{
    __shared__ float tile[32][33];
    const int n0 = blockIdx.x * 32, k0 = blockIdx.y * 32;
    const int tx = threadIdx.x, ty = threadIdx.y;  // 32 x 8
    #pragma unroll
    for (int i = 0; i < 32; i += 8)
        tile[ty + i][tx] = W[(size_t)(k0 + ty + i) * DD + n0 + tx];
    __syncthreads();
    #pragma unroll
    for (int i = 0; i < 32; i += 8) {
        float v = tile[tx][ty + i];   // W[k0+tx][n0+ty+i]
        __nv_bfloat16 h = __float2bfloat16(v);
        float r = v - __bfloat162float(h);
        size_t o = (size_t)(n0 + ty + i) * DD + k0 + tx;
        Th[o] = h;
        Tl[o] = __float2bfloat16(r);
    }
}

// ---------------------------------------------------------------------------
// Tensor-core GEMM via mma.sync (bf16 hi/lo, 3 products -> ~fp32 accuracy).
// C[M,N] = A[M,K] * B^T[N,K].  CTA tile 128x128, warp grid 2(M)x4(N),
// warp tile 64x32. K chunked by 32, double-buffered cp.async.
// smem row stride = 40 bf16 (80B): conflict-free ldmatrix, no swizzle.
// PERMUTE=true: scatter [B*S, H*DK] -> [B,H,S,DK].
// ---------------------------------------------------------------------------
#define KCH   32
#define TSTR  40                         // smem row stride in bf16 elems
#define TILE_B (128 * TSTR * 2)          // 10240 bytes per tile
#define STAGE_B (4 * TILE_B)             // 40960 bytes per stage

template<bool PERMUTE>
__global__ __launch_bounds__(256, 1)
void mma_gemm_kernel(const __nv_bfloat16* __restrict__ Ah, const __nv_bfloat16* __restrict__ Al,
                     const __nv_bfloat16* __restrict__ Bh, const __nv_bfloat16* __restrict__ Bl,
                     float* __restrict__ C)
{
    constexpr int Kdim = DD, Ndim = DD;
    extern __shared__ char smem_raw[];
    const uint32_t sbase = cvta_s(smem_raw);

    const int tid  = threadIdx.x;
    const int wid  = tid >> 5, lane = tid & 31;
    const int wm   = wid & 1;            // 0..1  (M)
    const int wn   = wid >> 1;           // 0..3  (N)
    const int m0   = blockIdx.y * 128, n0 = blockIdx.x * 128;

    float acc[4][4][4] = {};             // [i rowblk][j nblk][4]

    // -- chunk loader: 4 tiles of [128 rows x 32 bf16] --
    auto load_chunk = [&](int k0, int stage) {
        const uint32_t so = sbase + stage * STAGE_B;
        const int s0 = tid * 2;
        #pragma unroll
        for (int t2 = 0; t2 < 2; t2++) {
            const int s   = s0 + t2;            // 0..511
            const int row = s >> 2;
            const int ce  = (s & 3) * 8;        // elem offset in chunk
            const uint32_t sw = (row * TSTR + ce) * 2;
            const size_t ga = (size_t)(m0 + row) * Kdim + k0 + ce;
            const size_t gb = (size_t)(n0 + row) * Kdim + k0 + ce;
            CP_ASYNC16(so + sw,              Ah + ga);
            CP_ASYNC16(so + TILE_B + sw,     Al + ga);
            CP_ASYNC16(so + 2 * TILE_B + sw, Bh + gb);
            CP_ASYNC16(so + 3 * TILE_B + sw, Bl + gb);
        }
        CP_ASYNC_COMMIT();
    };

    // fragment smem addresses (per-lane, hoisted)
    const uint32_t a_row = wm * 64 + (lane & 15);
    const uint32_t a_col = (lane >> 4) * 8;
    const uint32_t b_row = wn * 32 + (lane & 7);
    const uint32_t b_col = ((lane >> 3) & 1) * 8;

    auto compute = [&](int stage) {
        const uint32_t so  = sbase + stage * STAGE_B;
        #pragma unroll
        for (int ks = 0; ks < 2; ks++) {
            uint32_t ah[4][4], al[4][4], bh[4][2], bl[4][2];
            #pragma unroll
            for (int i = 0; i < 4; i++) {
                const uint32_t off = ((a_row + i * 16) * TSTR + ks * 16 + a_col) * 2;
                LDMATRIX_X4(ah[i][0], ah[i][1], ah[i][2], ah[i][3], so + off);
                LDMATRIX_X4(al[i][0], al[i][1], al[i][2], al[i][3], so + TILE_B + off);
            }
            #pragma unroll
            for (int j = 0; j < 4; j++) {
                const uint32_t off = ((b_row + j * 8) * TSTR + ks * 16 + b_col) * 2;
                LDMATRIX_X2(bh[j][0], bh[j][1], so + 2 * TILE_B + off);
                LDMATRIX_X2(bl[j][0], bl[j][1], so + 3 * TILE_B + off);
            }
            #pragma unroll
            for (int i = 0; i < 4; i++)
                #pragma unroll
                for (int j = 0; j < 4; j++)
                    MMA_BF16(acc[i][j], ah[i], bh[j]);
            #pragma unroll
            for (int i = 0; i < 4; i++)
                #pragma unroll
                for (int j = 0; j < 4; j++)
                    MMA_BF16(acc[i][j], ah[i], bl[j]);
            #pragma unroll
            for (int i = 0; i < 4; i++)
                #pragma unroll
                for (int j = 0; j < 4; j++)
                    MMA_BF16(acc[i][j], al[i], bh[j]);
        }
    };

    load_chunk(0, 0);
    const int NCHUNK = Kdim / KCH;       // 32
    for (int c = 0; c < NCHUNK; c++) {
        if (c + 1 < NCHUNK) {
            load_chunk((c + 1) * KCH, (c + 1) & 1);
            CP_ASYNC_WAIT(1);
        } else {
            CP_ASYNC_WAIT(0);
        }
        __syncthreads();
        compute(c & 1);
        __syncthreads();
    }

    // -- epilogue: thread holds c0,c1 @ (row = l>>2, col = 2*(l&3)), c2,c3 @ row+8
    #pragma unroll
    for (int i = 0; i < 4; i++) {
        #pragma unroll
        for (int j = 0; j < 4; j++) {
            const int col = n0 + wn * 32 + j * 8 + 2 * (lane & 3);
            #pragma unroll
            for (int hlf = 0; hlf < 2; hlf++) {
                const int row = m0 + wm * 64 + i * 16 + (lane >> 2) + hlf * 8;
                float* p;
                if (PERMUTE) {
                    const int b = row >> 10, s = row & 1023;
                    const int h = col >> 6, dk = col & 63;
                    p = C + ((size_t)(b * HH + h) * SS + s) * DKK + dk;
                } else {
                    p = C + (size_t)row * Ndim + col;
                }
                *(float2*)p = make_float2(acc[i][j][hlf * 2], acc[i][j][hlf * 2 + 1]);
            }
        }
    }
}

// ---------------- flash attention (unchanged from R1) ----------------------
__global__ __launch_bounds__(64)
void flash_kernel(const float* __restrict__ bias, const float* __restrict__ bt,
                  float* __restrict__ O)
{
    constexpr int BQ = 64, BKV = 64;
    __shared__ float Ks[BKV][DKK];
    __shared__ float Vs[BKV][DKK];
    __shared__ float Sc[BKV][BQ];

    const int t  = threadIdx.x;
    const int qb = blockIdx.x * BQ;
    const int h  = blockIdx.y;
    const int b  = blockIdx.z;

    const float* Qp = g_Q + ((size_t)(b * HH + h) * SS + qb + t) * DKK;
    float q[DKK];
    #pragma unroll
    for (int d = 0; d < DKK; d += 4) {
        float4 v = *(const float4*)(Qp + d);
        q[d] = v.x; q[d+1] = v.y; q[d+2] = v.z; q[d+3] = v.w;
    }

    const float  btv     = bt[h];
    const float* biasRow = bias + (size_t)(qb + t) * SS;

    float m = -CUDART_INF_F;
    float l = 0.f;
    float o[DKK] = {};

    const float* Kb = g_K + (size_t)(b * HH + h) * SS * DKK;
    const float* Vb = g_V + (size_t)(b * HH + h) * SS * DKK;

    for (int kb = 0; kb < SS; kb += BKV) {
        __syncthreads();
        #pragma unroll
        for (int u = 0; u < 16; u++) {
            const int idx = t + u * 64;
            const int row = idx >> 4;
            const int c4  = (idx & 15) << 2;
            *(float4*)&Ks[row][c4] = *(const float4*)(Kb + (size_t)(kb + row) * DKK + c4);
            *(float4*)&Vs[row][c4] = *(const float4*)(Vb + (size_t)(kb + row) * DKK + c4);
        }
        __syncthreads();

        float tmax = m;
        #pragma unroll 1
        for (int j4 = 0; j4 < BKV; j4 += 4) {
            float4 bv = *(const float4*)(biasRow + kb + j4);
            float bb4[4] = {bv.x, bv.y, bv.z, bv.w};
            #pragma unroll
            for (int jj = 0; jj < 4; jj++) {
                const int j = j4 + jj;
                const float4* Kr = (const float4*)Ks[j];
                float s0 = 0.f, s1 = 0.f, s2 = 0.f, s3 = 0.f;
                #pragma unroll
                for (int d4 = 0; d4 < 16; d4++) {
                    float4 kv = Kr[d4];
                    s0 = fmaf(q[d4*4+0], kv.x, s0);
                    s1 = fmaf(q[d4*4+1], kv.y, s1);
                    s2 = fmaf(q[d4*4+2], kv.z, s2);
                    s3 = fmaf(q[d4*4+3], kv.w, s3);
                }
                float s = fmaf(btv, bb4[jj], ((s0 + s1) + (s2 + s3)) * 0.125f);
                Sc[j][t] = s;
                tmax = fmaxf(tmax, s);
            }
        }

        const float scale = __expf(m - tmax);
        m = tmax;
        l *= scale;
        #pragma unroll
        for (int d = 0; d < DKK; d++) o[d] *= scale;

        #pragma unroll 1
        for (int j = 0; j < BKV; j++) {
            const float p = __expf(Sc[j][t] - m);
            l += p;
            const float4* Vr = (const float4*)Vs[j];
            #pragma unroll
            for (int d4 = 0; d4 < 16; d4++) {
                float4 vv = Vr[d4];
                o[d4*4+0] = fmaf(p, vv.x, o[d4*4+0]);
                o[d4*4+1] = fmaf(p, vv.y, o[d4*4+1]);
                o[d4*4+2] = fmaf(p, vv.z, o[d4*4+2]);
                o[d4*4+3] = fmaf(p, vv.w, o[d4*4+3]);
            }
        }
    }

    const float inv = 1.f / l;
    float* Op = O + ((size_t)(b * SS) + qb + t) * (HH * DKK) + h * DKK;
    #pragma unroll
    for (int d = 0; d < DKK; d += 4) {
        float4 v = make_float4(o[d]*inv, o[d+1]*inv, o[d+2]*inv, o[d+3]*inv);
        *(float4*)(Op + d) = v;
    }
}

// ---------------- launch ---------------------------------------------------
extern "C" void kernel_launch(void* const* d_in, const int* in_sizes, int n_in,
                              void* d_out, int out_size)
{
    (void)in_sizes; (void)n_in; (void)out_size;
    const float* X    = (const float*)d_in[0];
    const float* bias = (const float*)d_in[1];
    const float* Wmat[4] = { (const float*)d_in[2], (const float*)d_in[3],
                             (const float*)d_in[4], (const float*)d_in[5] };
    const float* bt = (const float*)d_in[6];
    float* out = (float*)d_out;

    float *Qp, *Kp, *Vp, *Op;
    __nv_bfloat16 *Ahp, *Alp, *Whp, *Wlp;
    cudaGetSymbolAddress((void**)&Qp,  g_Q);
    cudaGetSymbolAddress((void**)&Kp,  g_K);
    cudaGetSymbolAddress((void**)&Vp,  g_V);
    cudaGetSymbolAddress((void**)&Op,  g_O);
    cudaGetSymbolAddress((void**)&Ahp, g_Ah);
    cudaGetSymbolAddress((void**)&Alp, g_Al);
    cudaGetSymbolAddress((void**)&Whp, g_Wh);
    cudaGetSymbolAddress((void**)&Wlp, g_Wl);

    const int SMEM_SZ = 2 * STAGE_B;   // 81920
    cudaFuncSetAttribute(mma_gemm_kernel<true>,
                         cudaFuncAttributeMaxDynamicSharedMemorySize, SMEM_SZ);
    cudaFuncSetAttribute(mma_gemm_kernel<false>,
                         cudaFuncAttributeMaxDynamicSharedMemorySize, SMEM_SZ);

    // X -> hi/lo bf16
    convert_hl_kernel<<<(MM * DD) / 1024, 256>>>(X, Ahp, Alp);
    // W -> transposed hi/lo bf16
    for (int w = 0; w < 4; w++)
        convert_wt_kernel<<<dim3(32, 32), dim3(32, 8)>>>(
            Wmat[w], Whp + (size_t)w * DD * DD, Wlp + (size_t)w * DD * DD);

    dim3 ggrid(DD / 128, MM / 128);   // (8, 128)
    mma_gemm_kernel<true><<<ggrid, 256, SMEM_SZ>>>(Ahp, Alp, Whp + 0*(size_t)DD*DD, Wlp + 0*(size_t)DD*DD, Qp);
    mma_gemm_kernel<true><<<ggrid, 256, SMEM_SZ>>>(Ahp, Alp, Whp + 1*(size_t)DD*DD, Wlp + 1*(size_t)DD*DD, Kp);
    mma_gemm_kernel<true><<<ggrid, 256, SMEM_SZ>>>(Ahp, Alp, Whp + 2*(size_t)DD*DD, Wlp + 2*(size_t)DD*DD, Vp);

    flash_kernel<<<dim3(SS / 64, HH, BB), 64>>>(bias, bt, Op);

    // O -> hi/lo bf16 (reuse X buffers), then final projection into d_out
    convert_hl_kernel<<<(MM * DD) / 1024, 256>>>(Op, Ahp, Alp);
    mma_gemm_kernel<false><<<ggrid, 256, SMEM_SZ>>>(Ahp, Alp, Whp + 3*(size_t)DD*DD, Wlp + 3*(size_t)DD*DD, out);
}

// round 5
// speedup vs baseline: 2.4076x; 1.6386x over previous
#include <cuda_runtime.h>
#include <cuda_bf16.h>
#include <math_constants.h>
#include <cstdint>

#define BB  16
#define SS  1024
#define DD  1024
#define HH  16
#define DKK 64
#define MM  (BB*SS)          // 16384

// ---------------- scratch (__device__ globals; no runtime allocs) ----------
__device__ float g_O[MM*DD];
__device__ __nv_bfloat16 g_Ah[MM*DD];     // hi of X, later hi of O
__device__ __nv_bfloat16 g_Al[MM*DD];     // lo of X, later lo of O
__device__ __nv_bfloat16 g_Wh[4][DD*DD];  // transposed weights, hi
__device__ __nv_bfloat16 g_Wl[4][DD*DD];  // transposed weights, lo
__device__ __nv_bfloat16 g_Qh[BB*HH*SS*DKK];
__device__ __nv_bfloat16 g_Ql[BB*HH*SS*DKK];
__device__ __nv_bfloat16 g_Kh[BB*HH*SS*DKK];
__device__ __nv_bfloat16 g_Kl[BB*HH*SS*DKK];
__device__ __nv_bfloat16 g_Vh[BB*HH*SS*DKK];
__device__ __nv_bfloat16 g_Vl[BB*HH*SS*DKK];

// ---------------- PTX helpers (sm_80-era only: valid in base sm_103 PTX) ---
__device__ __forceinline__ uint32_t cvta_s(const void* p) {
    return (uint32_t)__cvta_generic_to_shared(p);
}
#define CP_ASYNC16(saddr, gptr) \
    asm volatile("cp.async.cg.shared.global [%0], [%1], 16;" \
                 :: "r"((uint32_t)(saddr)), "l"(gptr))
#define CP_ASYNC_COMMIT() asm volatile("cp.async.commit_group;" ::: "memory")
#define CP_ASYNC_WAIT(n)  asm volatile("cp.async.wait_group %0;" :: "n"(n) : "memory")

#define LDMATRIX_X4(r0, r1, r2, r3, addr) \
    asm volatile("ldmatrix.sync.aligned.m8n8.x4.shared.b16 {%0,%1,%2,%3}, [%4];" \
                 : "=r"(r0), "=r"(r1), "=r"(r2), "=r"(r3) : "r"(addr))
#define LDMATRIX_X4T(r0, r1, r2, r3, addr) \
    asm volatile("ldmatrix.sync.aligned.m8n8.x4.trans.shared.b16 {%0,%1,%2,%3}, [%4];" \
                 : "=r"(r0), "=r"(r1), "=r"(r2), "=r"(r3) : "r"(addr))
#define LDMATRIX_X2(r0, r1, addr) \
    asm volatile("ldmatrix.sync.aligned.m8n8.x2.shared.b16 {%0,%1}, [%2];" \
                 : "=r"(r0), "=r"(r1) : "r"(addr))

__device__ __forceinline__ void mma_bf16(float* d, const uint32_t* a, uint32_t b0, uint32_t b1) {
    asm volatile("mma.sync.aligned.m16n8k16.row.col.f32.bf16.bf16.f32 "
        "{%0,%1,%2,%3}, {%4,%5,%6,%7}, {%8,%9}, {%0,%1,%2,%3};"
        : "+f"(d[0]), "+f"(d[1]), "+f"(d[2]), "+f"(d[3])
        : "r"(a[0]), "r"(a[1]), "r"(a[2]), "r"(a[3]), "r"(b0), "r"(b1));
}

__device__ __forceinline__ uint32_t pack2bf(float x, float y) {
    __nv_bfloat162 t = __floats2bfloat162_rn(x, y);
    return *reinterpret_cast<uint32_t*>(&t);
}
// split pair into hi/lo packed bf16x2
__device__ __forceinline__ void split2(float x, float y, uint32_t& hi, uint32_t& lo) {
    __nv_bfloat16 hx = __float2bfloat16(x), hy = __float2bfloat16(y);
    float rx = x - __bfloat162float(hx);
    float ry = y - __bfloat162float(hy);
    __nv_bfloat162 h2; h2.x = hx; h2.y = hy;
    hi = *reinterpret_cast<uint32_t*>(&h2);
    lo = pack2bf(rx, ry);
}

// ---------------- fp32 -> bf16 hi/lo split ---------------------------------
__global__ __launch_bounds__(256)
void convert_hl_kernel(const float* __restrict__ X,
                       __nv_bfloat16* __restrict__ H, __nv_bfloat16* __restrict__ L)
{
    const size_t i = ((size_t)blockIdx.x * 256 + threadIdx.x) * 4;
    float4 v = *(const float4*)(X + i);
    float f[4] = {v.x, v.y, v.z, v.w};
    ushort4 hv, lv;
    unsigned short* hp = &hv.x; unsigned short* lp = &lv.x;
    #pragma unroll
    for (int j = 0; j < 4; j++) {
        __nv_bfloat16 h = __float2bfloat16(f[j]);
        float r = f[j] - __bfloat162float(h);
        hp[j] = __bfloat16_as_ushort(h);
        lp[j] = __bfloat16_as_ushort(__float2bfloat16(r));
    }
    *(ushort4*)(H + i) = hv;
    *(ushort4*)(L + i) = lv;
}

// ---------------- W [K,N] -> W^T [N,K], split hi/lo ------------------------
__global__ __launch_bounds__(256)
void convert_wt_kernel(const float* __restrict__ W,
                       __nv_bfloat16* __restrict__ Th, __nv_bfloat16* __restrict__ Tl)
{
    __shared__ float tile[32][33];
    const int n0 = blockIdx.x * 32, k0 = blockIdx.y * 32;
    const int tx = threadIdx.x, ty = threadIdx.y;  // 32 x 8
    #pragma unroll
    for (int i = 0; i < 32; i += 8)
        tile[ty + i][tx] = W[(size_t)(k0 + ty + i) * DD + n0 + tx];
    __syncthreads();
    #pragma unroll
    for (int i = 0; i < 32; i += 8) {
        float v = tile[tx][ty + i];   // W[k0+tx][n0+ty+i]
        __nv_bfloat16 h = __float2bfloat16(v);
        float r = v - __bfloat162float(h);
        size_t o = (size_t)(n0 + ty + i) * DD + k0 + tx;
        Th[o] = h;
        Tl[o] = __float2bfloat16(r);
    }
}

// ---------------------------------------------------------------------------
// Tensor-core GEMM via mma.sync (bf16 hi/lo, 3 products -> ~fp32 accuracy).
// MODE 0: fp32 C[M,N].  MODE 1: permuted bf16 hi/lo output to (Ch, Cl) in
// [B,H,S,DK] layout (feeds the flash kernel directly).
// ---------------------------------------------------------------------------
#define KCH   32
#define TSTR  40                         // smem row stride in bf16 elems
#define TILE_B (128 * TSTR * 2)          // 10240 bytes per tile
#define STAGE_B (4 * TILE_B)             // 40960 bytes per stage

template<int MODE>
__global__ __launch_bounds__(256, 1)
void mma_gemm_kernel(const __nv_bfloat16* __restrict__ Ah, const __nv_bfloat16* __restrict__ Al,
                     const __nv_bfloat16* __restrict__ Bh, const __nv_bfloat16* __restrict__ Bl,
                     float* __restrict__ C,
                     __nv_bfloat16* __restrict__ Ch, __nv_bfloat16* __restrict__ Cl)
{
    constexpr int Kdim = DD, Ndim = DD;
    extern __shared__ char smem_raw[];
    const uint32_t sbase = cvta_s(smem_raw);

    const int tid  = threadIdx.x;
    const int wid  = tid >> 5, lane = tid & 31;
    const int wm   = wid & 1;            // 0..1  (M)
    const int wn   = wid >> 1;           // 0..3  (N)
    const int m0   = blockIdx.y * 128, n0 = blockIdx.x * 128;

    float acc[4][4][4] = {};             // [i rowblk][j nblk][4]

    auto load_chunk = [&](int k0, int stage) {
        const uint32_t so = sbase + stage * STAGE_B;
        const int s0 = tid * 2;
        #pragma unroll
        for (int t2 = 0; t2 < 2; t2++) {
            const int s   = s0 + t2;            // 0..511
            const int row = s >> 2;
            const int ce  = (s & 3) * 8;
            const uint32_t sw = (row * TSTR + ce) * 2;
            const size_t ga = (size_t)(m0 + row) * Kdim + k0 + ce;
            const size_t gb = (size_t)(n0 + row) * Kdim + k0 + ce;
            CP_ASYNC16(so + sw,              Ah + ga);
            CP_ASYNC16(so + TILE_B + sw,     Al + ga);
            CP_ASYNC16(so + 2 * TILE_B + sw, Bh + gb);
            CP_ASYNC16(so + 3 * TILE_B + sw, Bl + gb);
        }
        CP_ASYNC_COMMIT();
    };

    const uint32_t a_row = wm * 64 + (lane & 15);
    const uint32_t a_col = (lane >> 4) * 8;
    const uint32_t b_row = wn * 32 + (lane & 7);
    const uint32_t b_col = ((lane >> 3) & 1) * 8;

    auto compute = [&](int stage) {
        const uint32_t so  = sbase + stage * STAGE_B;
        #pragma unroll
        for (int ks = 0; ks < 2; ks++) {
            uint32_t ah[4][4], al[4][4], bh[4][2], bl[4][2];
            #pragma unroll
            for (int i = 0; i < 4; i++) {
                const uint32_t off = ((a_row + i * 16) * TSTR + ks * 16 + a_col) * 2;
                LDMATRIX_X4(ah[i][0], ah[i][1], ah[i][2], ah[i][3], so + off);
                LDMATRIX_X4(al[i][0], al[i][1], al[i][2], al[i][3], so + TILE_B + off);
            }
            #pragma unroll
            for (int j = 0; j < 4; j++) {
                const uint32_t off = ((b_row + j * 8) * TSTR + ks * 16 + b_col) * 2;
                LDMATRIX_X2(bh[j][0], bh[j][1], so + 2 * TILE_B + off);
                LDMATRIX_X2(bl[j][0], bl[j][1], so + 3 * TILE_B + off);
            }
            #pragma unroll
            for (int i = 0; i < 4; i++)
                #pragma unroll
                for (int j = 0; j < 4; j++)
                    mma_bf16(acc[i][j], ah[i], bh[j][0], bh[j][1]);
            #pragma unroll
            for (int i = 0; i < 4; i++)
                #pragma unroll
                for (int j = 0; j < 4; j++)
                    mma_bf16(acc[i][j], ah[i], bl[j][0], bl[j][1]);
            #pragma unroll
            for (int i = 0; i < 4; i++)
                #pragma unroll
                for (int j = 0; j < 4; j++)
                    mma_bf16(acc[i][j], al[i], bh[j][0], bh[j][1]);
        }
    };

    load_chunk(0, 0);
    const int NCHUNK = Kdim / KCH;       // 32
    for (int c = 0; c < NCHUNK; c++) {
        if (c + 1 < NCHUNK) {
            load_chunk((c + 1) * KCH, (c + 1) & 1);
            CP_ASYNC_WAIT(1);
        } else {
            CP_ASYNC_WAIT(0);
        }
        __syncthreads();
        compute(c & 1);
        __syncthreads();
    }

    #pragma unroll
    for (int i = 0; i < 4; i++) {
        #pragma unroll
        for (int j = 0; j < 4; j++) {
            const int col = n0 + wn * 32 + j * 8 + 2 * (lane & 3);
            #pragma unroll
            for (int hlf = 0; hlf < 2; hlf++) {
                const int row = m0 + wm * 64 + i * 16 + (lane >> 2) + hlf * 8;
                const float v0 = acc[i][j][hlf * 2], v1 = acc[i][j][hlf * 2 + 1];
                if (MODE == 0) {
                    float* p = C + (size_t)row * Ndim + col;
                    *(float2*)p = make_float2(v0, v1);
                } else {
                    const int b = row >> 10, s = row & 1023;
                    const int h = col >> 6, dk = col & 63;
                    const size_t off = ((size_t)(b * HH + h) * SS + s) * DKK + dk;
                    uint32_t hi, lo;
                    split2(v0, v1, hi, lo);
                    *(uint32_t*)(Ch + off) = hi;
                    *(uint32_t*)(Cl + off) = lo;
                }
            }
        }
    }
}

// ---------------------------------------------------------------------------
// Flash attention on mma.sync (bf16 hi/lo, 3 products each for QK^T and PV).
// Block: 64 q-rows x (h, b). 128 threads, 4 warps split over M (16 rows each).
// K/V tiles of 64 keys, hi/lo bf16, double-buffered cp.async.
// smem rows padded to 144B -> conflict-free ldmatrix.
// ---------------------------------------------------------------------------
#define FT_B   9216                       // one 64x64 bf16 tile @ 144B rows
#define FSTG_B (4 * FT_B)                 // Kh,Kl,Vh,Vl per stage = 36864
#define FQH_OFF (2 * FSTG_B)              // 73728
#define FQL_OFF (FQH_OFF + FT_B)          // 82944
#define FSMEM   (FQL_OFF + FT_B)          // 92160

__global__ __launch_bounds__(128)
void flash_mma_kernel(const float* __restrict__ bias, const float* __restrict__ bt,
                      float* __restrict__ O)
{
    extern __shared__ char fsm[];
    const uint32_t sb = cvta_s(fsm);
    const int tid = threadIdx.x, wid = tid >> 5, lane = tid & 31;
    const int qb = blockIdx.x * 64, h = blockIdx.y, b = blockIdx.z;
    const int bh = b * HH + h;
    const float btv = bt[h];

    const __nv_bfloat16* Qhg = g_Qh + ((size_t)bh * SS + qb) * DKK;
    const __nv_bfloat16* Qlg = g_Ql + ((size_t)bh * SS + qb) * DKK;
    const __nv_bfloat16* Khg = g_Kh + (size_t)bh * SS * DKK;
    const __nv_bfloat16* Klg = g_Kl + (size_t)bh * SS * DKK;
    const __nv_bfloat16* Vhg = g_Vh + (size_t)bh * SS * DKK;
    const __nv_bfloat16* Vlg = g_Vl + (size_t)bh * SS * DKK;

    // Q load (its own cp.async group)
    #pragma unroll
    for (int u = 0; u < 4; u++) {
        const int id = tid + u * 128;            // 0..511
        const int row = id >> 3, c = id & 7;
        const uint32_t off = row * 144 + c * 16;
        CP_ASYNC16(sb + FQH_OFF + off, Qhg + row * 64 + c * 8);
        CP_ASYNC16(sb + FQL_OFF + off, Qlg + row * 64 + c * 8);
    }
    CP_ASYNC_COMMIT();

    auto load_kv = [&](int t, int stage) {
        const uint32_t so = sb + stage * FSTG_B;
        const size_t g0 = (size_t)(t * 64) * DKK;
        #pragma unroll
        for (int u = 0; u < 4; u++) {
            const int id = tid + u * 128;
            const int row = id >> 3, c = id & 7;
            const uint32_t off = row * 144 + c * 16;
            const size_t g = g0 + row * 64 + c * 8;
            CP_ASYNC16(so + off,            Khg + g);
            CP_ASYNC16(so + FT_B + off,     Klg + g);
            CP_ASYNC16(so + 2 * FT_B + off, Vhg + g);
            CP_ASYNC16(so + 3 * FT_B + off, Vlg + g);
        }
        CP_ASYNC_COMMIT();
    };

    load_kv(0, 0);
    CP_ASYNC_WAIT(1);       // Q group done (kv0 may still be in flight)
    __syncthreads();

    // Q a-fragments (4 k-steps x 4 regs, hi and lo)
    uint32_t qh[4][4], ql[4][4];
    {
        const uint32_t qrow = wid * 16 + (lane & 15);
        #pragma unroll
        for (int ks = 0; ks < 4; ks++) {
            const uint32_t ad = sb + FQH_OFF + qrow * 144 + ks * 32 + (lane >> 4) * 16;
            LDMATRIX_X4(qh[ks][0], qh[ks][1], qh[ks][2], qh[ks][3], ad);
            LDMATRIX_X4(ql[ks][0], ql[ks][1], ql[ks][2], ql[ks][3], ad + FT_B);
        }
    }

    float out[8][4] = {};
    float m0 = -CUDART_INF_F, m1 = -CUDART_INF_F;
    float l0 = 0.f, l1 = 0.f;

    const int r0g = qb + wid * 16 + (lane >> 2);   // global q row (first)
    const int cb0 = 2 * (lane & 3);                // col offset within 8-block

    for (int t = 0; t < 16; t++) {
        if (t > 0) __syncthreads();                // stage t-1 consumers done
        if (t < 15) { load_kv(t + 1, (t + 1) & 1); CP_ASYNC_WAIT(1); }
        else       { CP_ASYNC_WAIT(0); }
        __syncthreads();

        const uint32_t so = sb + (t & 1) * FSTG_B;

        // ---- S = Q K^T (hi/lo, 3 products) ----
        float sacc[8][4];
        #pragma unroll
        for (int nb = 0; nb < 8; nb++) {
            sacc[nb][0] = sacc[nb][1] = sacc[nb][2] = sacc[nb][3] = 0.f;
            uint32_t kA[4], kB[4], lA[4], lB[4];
            const uint32_t kad = so + (nb * 8 + (lane & 7)) * 144 + (lane >> 3) * 16;
            LDMATRIX_X4(kA[0], kA[1], kA[2], kA[3], kad);
            LDMATRIX_X4(kB[0], kB[1], kB[2], kB[3], kad + 64);
            LDMATRIX_X4(lA[0], lA[1], lA[2], lA[3], kad + FT_B);
            LDMATRIX_X4(lB[0], lB[1], lB[2], lB[3], kad + FT_B + 64);
            #pragma unroll
            for (int ks = 0; ks < 4; ks++) {
                const uint32_t bh0 = (ks < 2) ? kA[2*ks]     : kB[2*(ks-2)];
                const uint32_t bh1 = (ks < 2) ? kA[2*ks + 1] : kB[2*(ks-2) + 1];
                const uint32_t bl0 = (ks < 2) ? lA[2*ks]     : lB[2*(ks-2)];
                const uint32_t bl1 = (ks < 2) ? lA[2*ks + 1] : lB[2*(ks-2) + 1];
                mma_bf16(sacc[nb], qh[ks], bh0, bh1);
                mma_bf16(sacc[nb], qh[ks], bl0, bl1);
                mma_bf16(sacc[nb], ql[ks], bh0, bh1);
            }
        }

        // ---- scale + bias, row max ----
        float tmax0 = m0, tmax1 = m1;
        #pragma unroll
        for (int nb = 0; nb < 8; nb++) {
            const int colg = t * 64 + nb * 8 + cb0;
            const float2 b0 = *(const float2*)(bias + (size_t)r0g * SS + colg);
            const float2 b1 = *(const float2*)(bias + (size_t)(r0g + 8) * SS + colg);
            sacc[nb][0] = fmaf(btv, b0.x, sacc[nb][0] * 0.125f);
            sacc[nb][1] = fmaf(btv, b0.y, sacc[nb][1] * 0.125f);
            sacc[nb][2] = fmaf(btv, b1.x, sacc[nb][2] * 0.125f);
            sacc[nb][3] = fmaf(btv, b1.y, sacc[nb][3] * 0.125f);
            tmax0 = fmaxf(tmax0, fmaxf(sacc[nb][0], sacc[nb][1]));
            tmax1 = fmaxf(tmax1, fmaxf(sacc[nb][2], sacc[nb][3]));
        }
        tmax0 = fmaxf(tmax0, __shfl_xor_sync(0xFFFFFFFF, tmax0, 1));
        tmax0 = fmaxf(tmax0, __shfl_xor_sync(0xFFFFFFFF, tmax0, 2));
        tmax1 = fmaxf(tmax1, __shfl_xor_sync(0xFFFFFFFF, tmax1, 1));
        tmax1 = fmaxf(tmax1, __shfl_xor_sync(0xFFFFFFFF, tmax1, 2));

        const float sc0 = __expf(m0 - tmax0);
        const float sc1 = __expf(m1 - tmax1);
        m0 = tmax0; m1 = tmax1;
        l0 *= sc0;  l1 *= sc1;
        #pragma unroll
        for (int nb = 0; nb < 8; nb++) {
            out[nb][0] *= sc0; out[nb][1] *= sc0;
            out[nb][2] *= sc1; out[nb][3] *= sc1;
        }

        // ---- P = exp(S - m), pack bf16 hi/lo; row sums ----
        uint32_t ph[8][2], pl[8][2];
        float rs0 = 0.f, rs1 = 0.f;
        #pragma unroll
        for (int nb = 0; nb < 8; nb++) {
            const float p0 = __expf(sacc[nb][0] - m0);
            const float p1 = __expf(sacc[nb][1] - m0);
            const float p2 = __expf(sacc[nb][2] - m1);
            const float p3 = __expf(sacc[nb][3] - m1);
            rs0 += p0 + p1; rs1 += p2 + p3;
            split2(p0, p1, ph[nb][0], pl[nb][0]);
            split2(p2, p3, ph[nb][1], pl[nb][1]);
        }
        rs0 += __shfl_xor_sync(0xFFFFFFFF, rs0, 1);
        rs0 += __shfl_xor_sync(0xFFFFFFFF, rs0, 2);
        rs1 += __shfl_xor_sync(0xFFFFFFFF, rs1, 1);
        rs1 += __shfl_xor_sync(0xFFFFFFFF, rs1, 2);
        l0 += rs0; l1 += rs1;

        // ---- out += P V (hi/lo, 3 products) ----
        #pragma unroll
        for (int nb = 0; nb < 8; nb++) {
            uint32_t vA[4], vB[4], wA[4], wB[4];
            const uint32_t vad = so + 2 * FT_B
                               + ((lane & 7) + 8 * (lane >> 3)) * 144 + nb * 16;
            LDMATRIX_X4T(vA[0], vA[1], vA[2], vA[3], vad);
            LDMATRIX_X4T(vB[0], vB[1], vB[2], vB[3], vad + 32 * 144);
            LDMATRIX_X4T(wA[0], wA[1], wA[2], wA[3], vad + FT_B);
            LDMATRIX_X4T(wB[0], wB[1], wB[2], wB[3], vad + FT_B + 32 * 144);
            #pragma unroll
            for (int ks = 0; ks < 4; ks++) {
                const uint32_t vh0 = (ks < 2) ? vA[2*ks]     : vB[2*(ks-2)];
                const uint32_t vh1 = (ks < 2) ? vA[2*ks + 1] : vB[2*(ks-2) + 1];
                const uint32_t vl0 = (ks < 2) ? wA[2*ks]     : wB[2*(ks-2)];
                const uint32_t vl1 = (ks < 2) ? wA[2*ks + 1] : wB[2*(ks-2) + 1];
                uint32_t aH[4] = { ph[2*ks][0], ph[2*ks][1], ph[2*ks+1][0], ph[2*ks+1][1] };
                uint32_t aL[4] = { pl[2*ks][0], pl[2*ks][1], pl[2*ks+1][0], pl[2*ks+1][1] };
                mma_bf16(out[nb], aH, vh0, vh1);
                mma_bf16(out[nb], aH, vl0, vl1);
                mma_bf16(out[nb], aL, vh0, vh1);
            }
        }
    }

    // ---- normalize + store to g_O [B, S, H*DK] ----
    const float inv0 = 1.f / l0, inv1 = 1.f / l1;
    float* O0 = O + ((size_t)b * SS + r0g) * (HH * DKK) + h * DKK;
    float* O1 = O + ((size_t)b * SS + r0g + 8) * (HH * DKK) + h * DKK;
    #pragma unroll
    for (int nb = 0; nb < 8; nb++) {
        const int dk = nb * 8 + cb0;
        *(float2*)(O0 + dk) = make_float2(out[nb][0] * inv0, out[nb][1] * inv0);
        *(float2*)(O1 + dk) = make_float2(out[nb][2] * inv1, out[nb][3] * inv1);
    }
}

// ---------------- launch ---------------------------------------------------
extern "C" void kernel_launch(void* const* d_in, const int* in_sizes, int n_in,
                              void* d_out, int out_size)
{
    (void)in_sizes; (void)n_in; (void)out_size;
    const float* X    = (const float*)d_in[0];
    const float* bias = (const float*)d_in[1];
    const float* Wmat[4] = { (const float*)d_in[2], (const float*)d_in[3],
                             (const float*)d_in[4], (const float*)d_in[5] };
    const float* bt = (const float*)d_in[6];
    float* out = (float*)d_out;

    float* Op;
    __nv_bfloat16 *Ahp, *Alp, *Whp, *Wlp;
    __nv_bfloat16 *Qh, *Ql, *Kh, *Kl, *Vh, *Vl;
    cudaGetSymbolAddress((void**)&Op,  g_O);
    cudaGetSymbolAddress((void**)&Ahp, g_Ah);
    cudaGetSymbolAddress((void**)&Alp, g_Al);
    cudaGetSymbolAddress((void**)&Whp, g_Wh);
    cudaGetSymbolAddress((void**)&Wlp, g_Wl);
    cudaGetSymbolAddress((void**)&Qh,  g_Qh);
    cudaGetSymbolAddress((void**)&Ql,  g_Ql);
    cudaGetSymbolAddress((void**)&Kh,  g_Kh);
    cudaGetSymbolAddress((void**)&Kl,  g_Kl);
    cudaGetSymbolAddress((void**)&Vh,  g_Vh);
    cudaGetSymbolAddress((void**)&Vl,  g_Vl);

    const int SMEM_SZ = 2 * STAGE_B;   // 81920
    cudaFuncSetAttribute(mma_gemm_kernel<0>,
                         cudaFuncAttributeMaxDynamicSharedMemorySize, SMEM_SZ);
    cudaFuncSetAttribute(mma_gemm_kernel<1>,
                         cudaFuncAttributeMaxDynamicSharedMemorySize, SMEM_SZ);
    cudaFuncSetAttribute(flash_mma_kernel,
                         cudaFuncAttributeMaxDynamicSharedMemorySize, FSMEM);

    convert_hl_kernel<<<(MM * DD) / 1024, 256>>>(X, Ahp, Alp);
    for (int w = 0; w < 4; w++)
        convert_wt_kernel<<<dim3(32, 32), dim3(32, 8)>>>(
            Wmat[w], Whp + (size_t)w * DD * DD, Wlp + (size_t)w * DD * DD);

    dim3 ggrid(DD / 128, MM / 128);   // (8, 128)
    mma_gemm_kernel<1><<<ggrid, 256, SMEM_SZ>>>(Ahp, Alp,
        Whp + 0*(size_t)DD*DD, Wlp + 0*(size_t)DD*DD, nullptr, Qh, Ql);
    mma_gemm_kernel<1><<<ggrid, 256, SMEM_SZ>>>(Ahp, Alp,
        Whp + 1*(size_t)DD*DD, Wlp + 1*(size_t)DD*DD, nullptr, Kh, Kl);
    mma_gemm_kernel<1><<<ggrid, 256, SMEM_SZ>>>(Ahp, Alp,
        Whp + 2*(size_t)DD*DD, Wlp + 2*(size_t)DD*DD, nullptr, Vh, Vl);

    flash_mma_kernel<<<dim3(SS / 64, HH, BB), 128, FSMEM>>>(bias, bt, Op);

    convert_hl_kernel<<<(MM * DD) / 1024, 256>>>(Op, Ahp, Alp);
    mma_gemm_kernel<0><<<ggrid, 256, SMEM_SZ>>>(Ahp, Alp,
        Whp + 3*(size_t)DD*DD, Wlp + 3*(size_t)DD*DD, out, nullptr, nullptr);
}

// round 6
// speedup vs baseline: 2.6143x; 1.0859x over previous
#include <cuda_runtime.h>
#include <cuda_bf16.h>
#include <math_constants.h>
#include <cstdint>

#define BB  16
#define SS  1024
#define DD  1024
#define HH  16
#define DKK 64
#define MM  (BB*SS)          // 16384
#define QSZ (BB*HH*SS*DKK)   // 16M elems

// ---------------- scratch (__device__ globals; no runtime allocs) ----------
__device__ __nv_bfloat16 g_Ah[MM*DD];       // hi of X
__device__ __nv_bfloat16 g_Al[MM*DD];       // lo of X
__device__ __nv_bfloat16 g_Oh[MM*DD];       // hi of attention output
__device__ __nv_bfloat16 g_Ol[MM*DD];       // lo of attention output
__device__ __nv_bfloat16 g_Wh[4][DD*DD];    // transposed weights, hi
__device__ __nv_bfloat16 g_Wl[4][DD*DD];    // transposed weights, lo
__device__ __nv_bfloat16 g_QKVh[3][QSZ];    // Q,K,V hi  [B,H,S,DK]
__device__ __nv_bfloat16 g_QKVl[3][QSZ];    // Q,K,V lo

// ---------------- PTX helpers (sm_80-era only: valid in base sm_103 PTX) ---
__device__ __forceinline__ uint32_t cvta_s(const void* p) {
    return (uint32_t)__cvta_generic_to_shared(p);
}
#define CP_ASYNC16(saddr, gptr) \
    asm volatile("cp.async.cg.shared.global [%0], [%1], 16;" \
                 :: "r"((uint32_t)(saddr)), "l"(gptr))
#define CP_ASYNC_COMMIT() asm volatile("cp.async.commit_group;" ::: "memory")
#define CP_ASYNC_WAIT(n)  asm volatile("cp.async.wait_group %0;" :: "n"(n) : "memory")

#define LDMATRIX_X4(r0, r1, r2, r3, addr) \
    asm volatile("ldmatrix.sync.aligned.m8n8.x4.shared.b16 {%0,%1,%2,%3}, [%4];" \
                 : "=r"(r0), "=r"(r1), "=r"(r2), "=r"(r3) : "r"(addr))
#define LDMATRIX_X4T(r0, r1, r2, r3, addr) \
    asm volatile("ldmatrix.sync.aligned.m8n8.x4.trans.shared.b16 {%0,%1,%2,%3}, [%4];" \
                 : "=r"(r0), "=r"(r1), "=r"(r2), "=r"(r3) : "r"(addr))
#define LDMATRIX_X2(r0, r1, addr) \
    asm volatile("ldmatrix.sync.aligned.m8n8.x2.shared.b16 {%0,%1}, [%2];" \
                 : "=r"(r0), "=r"(r1) : "r"(addr))

__device__ __forceinline__ void mma_bf16(float* d, const uint32_t* a, uint32_t b0, uint32_t b1) {
    asm volatile("mma.sync.aligned.m16n8k16.row.col.f32.bf16.bf16.f32 "
        "{%0,%1,%2,%3}, {%4,%5,%6,%7}, {%8,%9}, {%0,%1,%2,%3};"
        : "+f"(d[0]), "+f"(d[1]), "+f"(d[2]), "+f"(d[3])
        : "r"(a[0]), "r"(a[1]), "r"(a[2]), "r"(a[3]), "r"(b0), "r"(b1));
}

__device__ __forceinline__ uint32_t pack2bf(float x, float y) {
    __nv_bfloat162 t = __floats2bfloat162_rn(x, y);
    return *reinterpret_cast<uint32_t*>(&t);
}
__device__ __forceinline__ void split2(float x, float y, uint32_t& hi, uint32_t& lo) {
    __nv_bfloat16 hx = __float2bfloat16(x), hy = __float2bfloat16(y);
    float rx = x - __bfloat162float(hx);
    float ry = y - __bfloat162float(hy);
    __nv_bfloat162 h2; h2.x = hx; h2.y = hy;
    hi = *reinterpret_cast<uint32_t*>(&h2);
    lo = pack2bf(rx, ry);
}

// ---------------- fp32 -> bf16 hi/lo split ---------------------------------
__global__ __launch_bounds__(256)
void convert_hl_kernel(const float* __restrict__ X,
                       __nv_bfloat16* __restrict__ H, __nv_bfloat16* __restrict__ L)
{
    const size_t i = ((size_t)blockIdx.x * 256 + threadIdx.x) * 4;
    float4 v = *(const float4*)(X + i);
    float f[4] = {v.x, v.y, v.z, v.w};
    ushort4 hv, lv;
    unsigned short* hp = &hv.x; unsigned short* lp = &lv.x;
    #pragma unroll
    for (int j = 0; j < 4; j++) {
        __nv_bfloat16 h = __float2bfloat16(f[j]);
        float r = f[j] - __bfloat162float(h);
        hp[j] = __bfloat16_as_ushort(h);
        lp[j] = __bfloat16_as_ushort(__float2bfloat16(r));
    }
    *(ushort4*)(H + i) = hv;
    *(ushort4*)(L + i) = lv;
}

// ---------------- W [K,N] -> W^T [N,K], split hi/lo ------------------------
__global__ __launch_bounds__(256)
void convert_wt_kernel(const float* __restrict__ W,
                       __nv_bfloat16* __restrict__ Th, __nv_bfloat16* __restrict__ Tl)
{
    __shared__ float tile[32][33];
    const int n0 = blockIdx.x * 32, k0 = blockIdx.y * 32;
    const int tx = threadIdx.x, ty = threadIdx.y;  // 32 x 8
    #pragma unroll
    for (int i = 0; i < 32; i += 8)
        tile[ty + i][tx] = W[(size_t)(k0 + ty + i) * DD + n0 + tx];
    __syncthreads();
    #pragma unroll
    for (int i = 0; i < 32; i += 8) {
        float v = tile[tx][ty + i];
        __nv_bfloat16 h = __float2bfloat16(v);
        float r = v - __bfloat162float(h);
        size_t o = (size_t)(n0 + ty + i) * DD + k0 + tx;
        Th[o] = h;
        Tl[o] = __float2bfloat16(r);
    }
}

// ---------------------------------------------------------------------------
// Tensor-core GEMM via mma.sync (bf16 hi/lo, 3 products -> ~fp32 accuracy).
// CTA 128x128, warps 2(M)x4(N) of 64x32. KCH=64, 3-stage cp.async ring,
// ONE __syncthreads per chunk.
// MODE 0: fp32 C.  MODE 1: permuted bf16 hi/lo out (blockIdx.z picks W / dst).
// ---------------------------------------------------------------------------
#define KCH    64
#define TSTR   72                        // smem row stride in bf16 elems (144B)
#define TILE_B (128 * TSTR * 2)          // 18432 bytes
#define STAGE_B (4 * TILE_B)             // 73728 bytes
#define GSTAGES 3
#define GSMEM  (GSTAGES * STAGE_B)       // 221184 bytes

template<int MODE>
__global__ __launch_bounds__(256, 1)
void mma_gemm_kernel(const __nv_bfloat16* __restrict__ Ah, const __nv_bfloat16* __restrict__ Al,
                     const __nv_bfloat16* __restrict__ Bh0, const __nv_bfloat16* __restrict__ Bl0,
                     float* __restrict__ C,
                     __nv_bfloat16* __restrict__ Ch0, __nv_bfloat16* __restrict__ Cl0)
{
    constexpr int Kdim = DD, Ndim = DD;
    extern __shared__ char smem_raw[];
    const uint32_t sbase = cvta_s(smem_raw);

    const int z = blockIdx.z;
    const __nv_bfloat16* Bh = Bh0 + (size_t)z * DD * DD;
    const __nv_bfloat16* Bl = Bl0 + (size_t)z * DD * DD;
    __nv_bfloat16* Ch = (MODE == 1) ? Ch0 + (size_t)z * QSZ : nullptr;
    __nv_bfloat16* Cl = (MODE == 1) ? Cl0 + (size_t)z * QSZ : nullptr;

    const int tid  = threadIdx.x;
    const int wid  = tid >> 5, lane = tid & 31;
    const int wm   = wid & 1;
    const int wn   = wid >> 1;
    const int m0   = blockIdx.y * 128, n0 = blockIdx.x * 128;

    float acc[4][4][4] = {};

    // chunk = [128 rows x 64 bf16] x 4 tiles. 1024 16B-lines/tile, 4/thread.
    auto load_chunk = [&](int c, int stage) {
        const uint32_t so = sbase + stage * STAGE_B;
        const int k0 = c * KCH;
        #pragma unroll
        for (int u = 0; u < 4; u++) {
            const int id  = tid + u * 256;       // 0..1023
            const int row = id >> 3, cl = id & 7;
            const uint32_t sw = row * (TSTR * 2) + cl * 16;
            const size_t ga = (size_t)(m0 + row) * Kdim + k0 + cl * 8;
            const size_t gb = (size_t)(n0 + row) * Kdim + k0 + cl * 8;
            CP_ASYNC16(so + sw,              Ah + ga);
            CP_ASYNC16(so + TILE_B + sw,     Al + ga);
            CP_ASYNC16(so + 2 * TILE_B + sw, Bh + gb);
            CP_ASYNC16(so + 3 * TILE_B + sw, Bl + gb);
        }
        CP_ASYNC_COMMIT();
    };

    const uint32_t a_row = wm * 64 + (lane & 15);
    const uint32_t a_sub = (lane >> 4) * 16;             // bytes within 16-col step
    const uint32_t b_row = wn * 32 + (lane & 7);
    const uint32_t b_sub = ((lane >> 3) & 1) * 16;

    auto compute = [&](int stage) {
        const uint32_t so = sbase + stage * STAGE_B;
        #pragma unroll
        for (int ks = 0; ks < 4; ks++) {
            uint32_t ah[4][4], al[4][4], bh[4][2], bl[4][2];
            #pragma unroll
            for (int i = 0; i < 4; i++) {
                const uint32_t off = (a_row + i * 16) * (TSTR * 2) + ks * 32 + a_sub;
                LDMATRIX_X4(ah[i][0], ah[i][1], ah[i][2], ah[i][3], so + off);
                LDMATRIX_X4(al[i][0], al[i][1], al[i][2], al[i][3], so + TILE_B + off);
            }
            #pragma unroll
            for (int j = 0; j < 4; j++) {
                const uint32_t off = (b_row + j * 8) * (TSTR * 2) + ks * 32 + b_sub;
                LDMATRIX_X2(bh[j][0], bh[j][1], so + 2 * TILE_B + off);
                LDMATRIX_X2(bl[j][0], bl[j][1], so + 3 * TILE_B + off);
            }
            #pragma unroll
            for (int i = 0; i < 4; i++)
                #pragma unroll
                for (int j = 0; j < 4; j++)
                    mma_bf16(acc[i][j], ah[i], bh[j][0], bh[j][1]);
            #pragma unroll
            for (int i = 0; i < 4; i++)
                #pragma unroll
                for (int j = 0; j < 4; j++)
                    mma_bf16(acc[i][j], ah[i], bl[j][0], bl[j][1]);
            #pragma unroll
            for (int i = 0; i < 4; i++)
                #pragma unroll
                for (int j = 0; j < 4; j++)
                    mma_bf16(acc[i][j], al[i], bh[j][0], bh[j][1]);
        }
    };

    const int NCHUNK = Kdim / KCH;       // 16
    load_chunk(0, 0);
    load_chunk(1, 1);
    #pragma unroll 1
    for (int c = 0; c < NCHUNK; c++) {
        if (c < NCHUNK - 1) { CP_ASYNC_WAIT(1); }   // chunk c done, c+1 flying
        else               { CP_ASYNC_WAIT(0); }
        __syncthreads();
        compute(c % 3);
        if (c + 2 < NCHUNK) load_chunk(c + 2, (c + 2) % 3);
    }

    #pragma unroll
    for (int i = 0; i < 4; i++) {
        #pragma unroll
        for (int j = 0; j < 4; j++) {
            const int col = n0 + wn * 32 + j * 8 + 2 * (lane & 3);
            #pragma unroll
            for (int hlf = 0; hlf < 2; hlf++) {
                const int row = m0 + wm * 64 + i * 16 + (lane >> 2) + hlf * 8;
                const float v0 = acc[i][j][hlf * 2], v1 = acc[i][j][hlf * 2 + 1];
                if (MODE == 0) {
                    float* p = C + (size_t)row * Ndim + col;
                    *(float2*)p = make_float2(v0, v1);
                } else {
                    const int b = row >> 10, s = row & 1023;
                    const int h = col >> 6, dk = col & 63;
                    const size_t off = ((size_t)(b * HH + h) * SS + s) * DKK + dk;
                    uint32_t hi, lo;
                    split2(v0, v1, hi, lo);
                    *(uint32_t*)(Ch + off) = hi;
                    *(uint32_t*)(Cl + off) = lo;
                }
            }
        }
    }
}

// ---------------------------------------------------------------------------
// Flash attention on mma.sync (bf16 hi/lo, 3 products for QK^T and PV).
// 64 q-rows x (h,b); 128 threads, 4 warps over M. 3-stage KV ring, 1 sync/tile.
// Emits O as bf16 hi/lo directly.
// ---------------------------------------------------------------------------
#define FT_B    9216                      // 64x64 bf16 tile @ 144B rows
#define FSTG_B  (4 * FT_B)                // Kh,Kl,Vh,Vl = 36864
#define FQH_OFF (3 * FSTG_B)              // 110592
#define FQL_OFF (FQH_OFF + FT_B)
#define FSMEM   (FQL_OFF + FT_B)          // 129024

__global__ __launch_bounds__(128)
void flash_mma_kernel(const float* __restrict__ bias, const float* __restrict__ bt,
                      __nv_bfloat16* __restrict__ Oh, __nv_bfloat16* __restrict__ Ol)
{
    extern __shared__ char fsm[];
    const uint32_t sb = cvta_s(fsm);
    const int tid = threadIdx.x, wid = tid >> 5, lane = tid & 31;
    const int qb = blockIdx.x * 64, h = blockIdx.y, b = blockIdx.z;
    const int bh = b * HH + h;
    const float btv = bt[h];

    const __nv_bfloat16* Qhg = g_QKVh[0] + ((size_t)bh * SS + qb) * DKK;
    const __nv_bfloat16* Qlg = g_QKVl[0] + ((size_t)bh * SS + qb) * DKK;
    const __nv_bfloat16* Khg = g_QKVh[1] + (size_t)bh * SS * DKK;
    const __nv_bfloat16* Klg = g_QKVl[1] + (size_t)bh * SS * DKK;
    const __nv_bfloat16* Vhg = g_QKVh[2] + (size_t)bh * SS * DKK;
    const __nv_bfloat16* Vlg = g_QKVl[2] + (size_t)bh * SS * DKK;

    // Q load (own group)
    #pragma unroll
    for (int u = 0; u < 4; u++) {
        const int id = tid + u * 128;            // 0..511
        const int row = id >> 3, c = id & 7;
        const uint32_t off = row * 144 + c * 16;
        CP_ASYNC16(sb + FQH_OFF + off, Qhg + row * 64 + c * 8);
        CP_ASYNC16(sb + FQL_OFF + off, Qlg + row * 64 + c * 8);
    }
    CP_ASYNC_COMMIT();

    auto load_kv = [&](int t, int stage) {
        const uint32_t so = sb + stage * FSTG_B;
        const size_t g0 = (size_t)(t * 64) * DKK;
        #pragma unroll
        for (int u = 0; u < 4; u++) {
            const int id = tid + u * 128;
            const int row = id >> 3, c = id & 7;
            const uint32_t off = row * 144 + c * 16;
            const size_t g = g0 + row * 64 + c * 8;
            CP_ASYNC16(so + off,            Khg + g);
            CP_ASYNC16(so + FT_B + off,     Klg + g);
            CP_ASYNC16(so + 2 * FT_B + off, Vhg + g);
            CP_ASYNC16(so + 3 * FT_B + off, Vlg + g);
        }
        CP_ASYNC_COMMIT();
    };

    load_kv(0, 0);
    load_kv(1, 1);
    CP_ASYNC_WAIT(2);       // Q group done
    __syncthreads();

    // Q fragments (4 k-steps x 4 regs, hi and lo)
    uint32_t qh[4][4], ql[4][4];
    {
        const uint32_t qrow = wid * 16 + (lane & 15);
        #pragma unroll
        for (int ks = 0; ks < 4; ks++) {
            const uint32_t ad = sb + FQH_OFF + qrow * 144 + ks * 32 + (lane >> 4) * 16;
            LDMATRIX_X4(qh[ks][0], qh[ks][1], qh[ks][2], qh[ks][3], ad);
            LDMATRIX_X4(ql[ks][0], ql[ks][1], ql[ks][2], ql[ks][3], ad + FT_B);
        }
    }

    float out[8][4] = {};
    float m0 = -CUDART_INF_F, m1 = -CUDART_INF_F;
    float l0 = 0.f, l1 = 0.f;

    const int r0g = qb + wid * 16 + (lane >> 2);
    const int cb0 = 2 * (lane & 3);

    #pragma unroll 1
    for (int t = 0; t < 16; t++) {
        if (t < 15) { CP_ASYNC_WAIT(1); }      // tile t done, t+1 flying
        else        { CP_ASYNC_WAIT(0); }
        __syncthreads();

        const uint32_t so = sb + (t % 3) * FSTG_B;

        // ---- S = Q K^T ----
        float sacc[8][4];
        #pragma unroll
        for (int nb = 0; nb < 8; nb++) {
            sacc[nb][0] = sacc[nb][1] = sacc[nb][2] = sacc[nb][3] = 0.f;
            uint32_t kA[4], kB[4], lA[4], lB[4];
            const uint32_t kad = so + (nb * 8 + (lane & 7)) * 144 + (lane >> 3) * 16;
            LDMATRIX_X4(kA[0], kA[1], kA[2], kA[3], kad);
            LDMATRIX_X4(kB[0], kB[1], kB[2], kB[3], kad + 64);
            LDMATRIX_X4(lA[0], lA[1], lA[2], lA[3], kad + FT_B);
            LDMATRIX_X4(lB[0], lB[1], lB[2], lB[3], kad + FT_B + 64);
            #pragma unroll
            for (int ks = 0; ks < 4; ks++) {
                const uint32_t bh0 = (ks < 2) ? kA[2*ks]     : kB[2*(ks-2)];
                const uint32_t bh1 = (ks < 2) ? kA[2*ks + 1] : kB[2*(ks-2) + 1];
                const uint32_t bl0 = (ks < 2) ? lA[2*ks]     : lB[2*(ks-2)];
                const uint32_t bl1 = (ks < 2) ? lA[2*ks + 1] : lB[2*(ks-2) + 1];
                mma_bf16(sacc[nb], qh[ks], bh0, bh1);
                mma_bf16(sacc[nb], qh[ks], bl0, bl1);
                mma_bf16(sacc[nb], ql[ks], bh0, bh1);
            }
        }

        // ---- scale + bias, row max ----
        float tmax0 = m0, tmax1 = m1;
        #pragma unroll
        for (int nb = 0; nb < 8; nb++) {
            const int colg = t * 64 + nb * 8 + cb0;
            const float2 b0 = *(const float2*)(bias + (size_t)r0g * SS + colg);
            const float2 b1 = *(const float2*)(bias + (size_t)(r0g + 8) * SS + colg);
            sacc[nb][0] = fmaf(btv, b0.x, sacc[nb][0] * 0.125f);
            sacc[nb][1] = fmaf(btv, b0.y, sacc[nb][1] * 0.125f);
            sacc[nb][2] = fmaf(btv, b1.x, sacc[nb][2] * 0.125f);
            sacc[nb][3] = fmaf(btv, b1.y, sacc[nb][3] * 0.125f);
            tmax0 = fmaxf(tmax0, fmaxf(sacc[nb][0], sacc[nb][1]));
            tmax1 = fmaxf(tmax1, fmaxf(sacc[nb][2], sacc[nb][3]));
        }
        tmax0 = fmaxf(tmax0, __shfl_xor_sync(0xFFFFFFFF, tmax0, 1));
        tmax0 = fmaxf(tmax0, __shfl_xor_sync(0xFFFFFFFF, tmax0, 2));
        tmax1 = fmaxf(tmax1, __shfl_xor_sync(0xFFFFFFFF, tmax1, 1));
        tmax1 = fmaxf(tmax1, __shfl_xor_sync(0xFFFFFFFF, tmax1, 2));

        const float sc0 = __expf(m0 - tmax0);
        const float sc1 = __expf(m1 - tmax1);
        m0 = tmax0; m1 = tmax1;
        l0 *= sc0;  l1 *= sc1;
        #pragma unroll
        for (int nb = 0; nb < 8; nb++) {
            out[nb][0] *= sc0; out[nb][1] *= sc0;
            out[nb][2] *= sc1; out[nb][3] *= sc1;
        }

        // ---- P = exp(S - m), bf16 hi/lo; row sums ----
        uint32_t ph[8][2], pl[8][2];
        float rs0 = 0.f, rs1 = 0.f;
        #pragma unroll
        for (int nb = 0; nb < 8; nb++) {
            const float p0 = __expf(sacc[nb][0] - m0);
            const float p1 = __expf(sacc[nb][1] - m0);
            const float p2 = __expf(sacc[nb][2] - m1);
            const float p3 = __expf(sacc[nb][3] - m1);
            rs0 += p0 + p1; rs1 += p2 + p3;
            split2(p0, p1, ph[nb][0], pl[nb][0]);
            split2(p2, p3, ph[nb][1], pl[nb][1]);
        }
        rs0 += __shfl_xor_sync(0xFFFFFFFF, rs0, 1);
        rs0 += __shfl_xor_sync(0xFFFFFFFF, rs0, 2);
        rs1 += __shfl_xor_sync(0xFFFFFFFF, rs1, 1);
        rs1 += __shfl_xor_sync(0xFFFFFFFF, rs1, 2);
        l0 += rs0; l1 += rs1;

        // ---- out += P V ----
        #pragma unroll
        for (int nb = 0; nb < 8; nb++) {
            uint32_t vA[4], vB[4], wA[4], wB[4];
            const uint32_t vad = so + 2 * FT_B
                               + ((lane & 7) + 8 * (lane >> 3)) * 144 + nb * 16;
            LDMATRIX_X4T(vA[0], vA[1], vA[2], vA[3], vad);
            LDMATRIX_X4T(vB[0], vB[1], vB[2], vB[3], vad + 32 * 144);
            LDMATRIX_X4T(wA[0], wA[1], wA[2], wA[3], vad + FT_B);
            LDMATRIX_X4T(wB[0], wB[1], wB[2], wB[3], vad + FT_B + 32 * 144);
            #pragma unroll
            for (int ks = 0; ks < 4; ks++) {
                const uint32_t vh0 = (ks < 2) ? vA[2*ks]     : vB[2*(ks-2)];
                const uint32_t vh1 = (ks < 2) ? vA[2*ks + 1] : vB[2*(ks-2) + 1];
                const uint32_t vl0 = (ks < 2) ? wA[2*ks]     : wB[2*(ks-2)];
                const uint32_t vl1 = (ks < 2) ? wA[2*ks + 1] : wB[2*(ks-2) + 1];
                uint32_t aH[4] = { ph[2*ks][0], ph[2*ks][1], ph[2*ks+1][0], ph[2*ks+1][1] };
                uint32_t aL[4] = { pl[2*ks][0], pl[2*ks][1], pl[2*ks+1][0], pl[2*ks+1][1] };
                mma_bf16(out[nb], aH, vh0, vh1);
                mma_bf16(out[nb], aH, vl0, vl1);
                mma_bf16(out[nb], aL, vh0, vh1);
            }
        }

        if (t + 2 < 16) load_kv(t + 2, (t + 2) % 3);
    }

    // ---- normalize + store O as bf16 hi/lo, [B, S, H*DK] ----
    const float inv0 = 1.f / l0, inv1 = 1.f / l1;
    const size_t o0 = ((size_t)b * SS + r0g) * (HH * DKK) + h * DKK;
    const size_t o1 = ((size_t)b * SS + r0g + 8) * (HH * DKK) + h * DKK;
    #pragma unroll
    for (int nb = 0; nb < 8; nb++) {
        const int dk = nb * 8 + cb0;
        uint32_t hi, lo;
        split2(out[nb][0] * inv0, out[nb][1] * inv0, hi, lo);
        *(uint32_t*)(Oh + o0 + dk) = hi;
        *(uint32_t*)(Ol + o0 + dk) = lo;
        split2(out[nb][2] * inv1, out[nb][3] * inv1, hi, lo);
        *(uint32_t*)(Oh + o1 + dk) = hi;
        *(uint32_t*)(Ol + o1 + dk) = lo;
    }
}

// ---------------- launch ---------------------------------------------------
extern "C" void kernel_launch(void* const* d_in, const int* in_sizes, int n_in,
                              void* d_out, int out_size)
{
    (void)in_sizes; (void)n_in; (void)out_size;
    const float* X    = (const float*)d_in[0];
    const float* bias = (const float*)d_in[1];
    const float* Wmat[4] = { (const float*)d_in[2], (const float*)d_in[3],
                             (const float*)d_in[4], (const float*)d_in[5] };
    const float* bt = (const float*)d_in[6];
    float* out = (float*)d_out;

    __nv_bfloat16 *Ahp, *Alp, *Ohp, *Olp, *Whp, *Wlp, *QKVh, *QKVl;
    cudaGetSymbolAddress((void**)&Ahp,  g_Ah);
    cudaGetSymbolAddress((void**)&Alp,  g_Al);
    cudaGetSymbolAddress((void**)&Ohp,  g_Oh);
    cudaGetSymbolAddress((void**)&Olp,  g_Ol);
    cudaGetSymbolAddress((void**)&Whp,  g_Wh);
    cudaGetSymbolAddress((void**)&Wlp,  g_Wl);
    cudaGetSymbolAddress((void**)&QKVh, g_QKVh);
    cudaGetSymbolAddress((void**)&QKVl, g_QKVl);

    cudaFuncSetAttribute(mma_gemm_kernel<0>,
                         cudaFuncAttributeMaxDynamicSharedMemorySize, GSMEM);
    cudaFuncSetAttribute(mma_gemm_kernel<1>,
                         cudaFuncAttributeMaxDynamicSharedMemorySize, GSMEM);
    cudaFuncSetAttribute(flash_mma_kernel,
                         cudaFuncAttributeMaxDynamicSharedMemorySize, FSMEM);

    convert_hl_kernel<<<(MM * DD) / 1024, 256>>>(X, Ahp, Alp);
    for (int w = 0; w < 4; w++)
        convert_wt_kernel<<<dim3(32, 32), dim3(32, 8)>>>(
            Wmat[w], Whp + (size_t)w * DD * DD, Wlp + (size_t)w * DD * DD);

    // fused Q/K/V projections: grid.z picks weight + destination
    dim3 qkv_grid(DD / 128, MM / 128, 3);
    mma_gemm_kernel<1><<<qkv_grid, 256, GSMEM>>>(Ahp, Alp, Whp, Wlp,
                                                 nullptr, QKVh, QKVl);

    flash_mma_kernel<<<dim3(SS / 64, HH, BB), 128, FSMEM>>>(bias, bt, Ohp, Olp);

    // output projection straight from bf16 hi/lo O
    dim3 ogrid(DD / 128, MM / 128, 1);
    mma_gemm_kernel<0><<<ogrid, 256, GSMEM>>>(Ohp, Olp,
        Whp + 3 * (size_t)DD * DD, Wlp + 3 * (size_t)DD * DD, out, nullptr, nullptr);
}